// round 15
// baseline (speedup 1.0000x reference)
#include <cuda_runtime.h>

#define NN 4096
#define MM 128
#define KK 32
#define GG 16
#define NS 8
#define CHUNK (NN / NS)   // 512

// Scratch (device globals: no runtime allocation allowed)
__device__ float  g_V[NN * KK];                // transported-solve vectors v_i
__device__ float  g_wmT[MM * NN];              // masked mean weights, [a][i]
__device__ float4 g_OP4[MM * 256];             // pre-reduced omega_parent mean
__device__ float  g_partZ[MM * NS];
__device__ float  g_partCnt[MM * NS];
__device__ float  g_partS1[MM * NS * KK];
__device__ float  g_partS2[MM * NS * KK * KK];
__device__ float  g_psiPart[MM * 4];

// Host-side stream/event plumbing (created once at load; NOT device memory).
struct HxStreams {
    cudaStream_t side;
    cudaEvent_t evRoot, evSide;
    HxStreams() {
        cudaStreamCreateWithFlags(&side, cudaStreamNonBlocking);
        cudaEventCreateWithFlags(&evRoot, cudaEventDisableTiming);
        cudaEventCreateWithFlags(&evSide, cudaEventDisableTiming);
    }
};
static HxStreams g_hx;

// ---------------------------------------------------------------------------
// Kernel 0: coalesced W reduce + mask + TRANSPOSE -> g_wmT[a][i].
// ---------------------------------------------------------------------------
__global__ void wreduce_kernel(const float* __restrict__ W)
{
    __shared__ float tile[32][129];
    const int i0 = blockIdx.x * 32;
    const int t = threadIdx.x;            // 0..255
    const int il = t >> 3;                // 0..31
    const int sub = t & 7;                // 0..7 -> a range sub*16..+15

    const float4* p = (const float4*)W + (size_t)(i0 + il) * 512 + sub * 64;
    #pragma unroll
    for (int aa = 0; aa < 16; aa++) {
        const float4 a0 = p[aa * 4 + 0];
        const float4 a1 = p[aa * 4 + 1];
        const float4 a2 = p[aa * 4 + 2];
        const float4 a3 = p[aa * 4 + 3];
        const float sum = (a0.x + a0.y + a0.z + a0.w)
                        + (a1.x + a1.y + a1.z + a1.w)
                        + (a2.x + a2.y + a2.z + a2.w)
                        + (a3.x + a3.y + a3.z + a3.w);
        const float wm = sum * 0.0625f;
        tile[il][sub * 16 + aa] = (wm >= 1e-6f) ? wm : 0.0f;
    }
    __syncthreads();

    const int a = t >> 1, hf = t & 1;
    float4 o0, o1, o2, o3;
    o0.x = tile[hf * 16 +  0][a]; o0.y = tile[hf * 16 +  1][a];
    o0.z = tile[hf * 16 +  2][a]; o0.w = tile[hf * 16 +  3][a];
    o1.x = tile[hf * 16 +  4][a]; o1.y = tile[hf * 16 +  5][a];
    o1.z = tile[hf * 16 +  6][a]; o1.w = tile[hf * 16 +  7][a];
    o2.x = tile[hf * 16 +  8][a]; o2.y = tile[hf * 16 +  9][a];
    o2.z = tile[hf * 16 + 10][a]; o2.w = tile[hf * 16 + 11][a];
    o3.x = tile[hf * 16 + 12][a]; o3.y = tile[hf * 16 + 13][a];
    o3.z = tile[hf * 16 + 14][a]; o3.w = tile[hf * 16 + 15][a];
    float4* dst = (float4*)(g_wmT + (size_t)a * NN + i0 + hf * 16);
    dst[0] = o0; dst[1] = o1; dst[2] = o2; dst[3] = o3;
}

// ---------------------------------------------------------------------------
// Kernel 1: fused reduce+solve, TWO systems per block with intra-block
// software pipelining: system 1's 16 G-reduction load steps ride under
// system 0's forward-elimination barriers (accumulated in registers, staged
// to smem after sys0's back-sub). Elimination math = R10 verbatim.
// ---------------------------------------------------------------------------
__global__ void solve_kernel(const float* __restrict__ omega_child,
                             const float* __restrict__ mu_s)
{
    __shared__ float A[KK * 33];
    const int i0 = blockIdx.x * 2;
    const int t = threadIdx.x;       // 0..127
    const int lane = t & 31, w = t >> 5;

    const float4* oc0 = (const float4*)(omega_child + (size_t)i0 * GG * KK * KK);
    const float4* oc1 = oc0 + GG * 256;
    const float* mu0 = mu_s + (size_t)i0 * GG * KK;
    const float* mu1 = mu0 + GG * KK;

    // ---- Phase 1: reduce sys0 over G (R10 pattern)
    #pragma unroll
    for (int h = 0; h < 2; h++) {
        const int q = t + h * 128;
        float4 s = make_float4(0.f, 0.f, 0.f, 0.f);
        #pragma unroll
        for (int g = 0; g < GG; g++) {
            const float4 v = oc0[g * 256 + q];
            s.x += v.x; s.y += v.y; s.z += v.z; s.w += v.w;
        }
        const int e = q * 4;
        const int r = e >> 5, c = e & 31;
        A[r * 33 + c + 0] = s.x;
        A[r * 33 + c + 1] = s.y;
        A[r * 33 + c + 2] = s.z;
        A[r * 33 + c + 3] = s.w;
    }
    if (t < KK) {
        float s = 0.f;
        #pragma unroll
        for (int g = 0; g < GG; g++) s += mu0[g * KK + t];
        A[t * 33 + 32] = s;
    }
    __syncthreads();

    // sys1 accumulators (pipelined loads)
    float4 b0 = make_float4(0.f, 0.f, 0.f, 0.f);
    float4 b1 = make_float4(0.f, 0.f, 0.f, 0.f);
    float bmu = 0.f;

    // ---- Forward elimination sys0 + pipelined sys1 loads (k<16)
    for (int k = 0; k < KK - 1; k++) {
        if (k < GG) {
            const float4 v0 = oc1[k * 256 + t];
            const float4 v1 = oc1[k * 256 + t + 128];
            b0.x += v0.x; b0.y += v0.y; b0.z += v0.z; b0.w += v0.w;
            b1.x += v1.x; b1.y += v1.y; b1.z += v1.z; b1.w += v1.w;
            if (t < KK) bmu += mu1[k * KK + t];
        }
        const float invp = 1.0f / A[k * 33 + k];
        const int c = k + 1 + lane;
        for (int r = k + 1 + w; r < KK; r += 4) {
            const float m = A[r * 33 + k] * invp;
            if (c <= 32) A[r * 33 + c] -= m * A[k * 33 + c];
        }
        __syncthreads();
    }

    // ---- Back-sub sys0
    for (int k = KK - 1; k >= 1; k--) {
        if (t < k) {
            const float xk = A[k * 33 + 32] / A[k * 33 + k];
            A[t * 33 + 32] -= A[t * 33 + k] * xk;
        }
        __syncthreads();
    }
    if (t < KK)
        g_V[(size_t)i0 * KK + t] = A[t * 33 + 32] / A[t * 33 + t];
    __syncthreads();                // all reads of A for sys0 complete

    // ---- Stage sys1 from registers into A (same q->slot map as phase 1)
    {
        const int e0 = t * 4;
        const int r0 = e0 >> 5, c0 = e0 & 31;
        A[r0 * 33 + c0 + 0] = b0.x;
        A[r0 * 33 + c0 + 1] = b0.y;
        A[r0 * 33 + c0 + 2] = b0.z;
        A[r0 * 33 + c0 + 3] = b0.w;
        const int e1 = (t + 128) * 4;
        const int r1 = e1 >> 5, c1 = e1 & 31;
        A[r1 * 33 + c1 + 0] = b1.x;
        A[r1 * 33 + c1 + 1] = b1.y;
        A[r1 * 33 + c1 + 2] = b1.z;
        A[r1 * 33 + c1 + 3] = b1.w;
    }
    if (t < KK) A[t * 33 + 32] = bmu;
    __syncthreads();

    // ---- Forward elimination + back-sub sys1
    for (int k = 0; k < KK - 1; k++) {
        const float invp = 1.0f / A[k * 33 + k];
        const int c = k + 1 + lane;
        for (int r = k + 1 + w; r < KK; r += 4) {
            const float m = A[r * 33 + k] * invp;
            if (c <= 32) A[r * 33 + c] -= m * A[k * 33 + c];
        }
        __syncthreads();
    }
    for (int k = KK - 1; k >= 1; k--) {
        if (t < k) {
            const float xk = A[k * 33 + 32] / A[k * 33 + k];
            A[t * 33 + 32] -= A[t * 33 + k] * xk;
        }
        __syncthreads();
    }
    if (t < KK)
        g_V[(size_t)(i0 + 1) * KK + t] = A[t * 33 + 32] / A[t * 33 + t];
}

// ---------------------------------------------------------------------------
// Kernel 1b: streaming mean of omega_parent over G -> g_OP4 (two halves so
// solve lands 4th for ncu).
// ---------------------------------------------------------------------------
__global__ void reduce_op_kernel(const float4* __restrict__ op4, int abase)
{
    const int gid = blockIdx.x * blockDim.x + threadIdx.x;
    const int a = abase + (gid >> 8);
    const int q = gid & 255;
    const float4* p = op4 + (size_t)a * (GG * 256) + q;
    float4 s0 = p[0];
    float4 s1 = p[256];
    #pragma unroll
    for (int g = 2; g < GG; g += 2) {
        const float4 va = p[g * 256];
        const float4 vb = p[(g + 1) * 256];
        s0.x += va.x; s0.y += va.y; s0.z += va.z; s0.w += va.w;
        s1.x += vb.x; s1.y += vb.y; s1.z += vb.z; s1.w += vb.w;
    }
    const float inv = 1.0f / 16.0f;
    s0.x = (s0.x + s1.x) * inv; s0.y = (s0.y + s1.y) * inv;
    s0.z = (s0.z + s1.z) * inv; s0.w = (s0.w + s1.w) * inv;
    g_OP4[a * 256 + q] = s0;
}

// ---------------------------------------------------------------------------
// Kernel 2: 8x8 register tile accum — R8/R10 VERBATIM (35.3us measured).
// FROZEN.
// ---------------------------------------------------------------------------
__global__ void __launch_bounds__(128, 3)
accum_kernel(void)
{
    const int a = blockIdx.x;
    const int s = blockIdx.y;
    const int t = threadIdx.x;     // 0..127
    const int i0base = s * CHUNK;

    __shared__ float sw[CHUNK];          // sqrt of masked mean weights (2 KB)
    __shared__ float sx[32 * 36];        // sqrt(w)*v tile, row stride 36
    __shared__ float zred[4], cred[4];

    // ---- Phase 0: coalesced wmT read (4 i's per thread)
    {
        const float4 wv =
            ((const float4*)(g_wmT + (size_t)a * NN + i0base))[t];
        float accZ = wv.x + wv.y + wv.z + wv.w;
        float accCnt = (wv.x > 0.f ? 1.f : 0.f) + (wv.y > 0.f ? 1.f : 0.f)
                     + (wv.z > 0.f ? 1.f : 0.f) + (wv.w > 0.f ? 1.f : 0.f);
        sw[4 * t + 0] = sqrtf(wv.x);
        sw[4 * t + 1] = sqrtf(wv.y);
        sw[4 * t + 2] = sqrtf(wv.z);
        sw[4 * t + 3] = sqrtf(wv.w);
        #pragma unroll
        for (int off = 16; off; off >>= 1) {
            accZ   += __shfl_xor_sync(0xffffffffu, accZ, off);
            accCnt += __shfl_xor_sync(0xffffffffu, accCnt, off);
        }
        if ((t & 31) == 0) { zred[t >> 5] = accZ; cred[t >> 5] = accCnt; }
    }
    __syncthreads();
    if (t == 0) {
        g_partZ[a * NS + s]   = zred[0] + zred[1] + zred[2] + zred[3];
        g_partCnt[a * NS + s] = cred[0] + cred[1] + cred[2] + cred[3];
    }

    const int ig = t >> 4;      // ii-group 0..7
    const int tl = t & 15;
    const int rt = tl >> 2;     // row-oct
    const int ct = tl & 3;      // col-oct
    const int ii_s = t >> 2;    // staging row 0..31
    const int cc_s = t & 3;     // staging quad 0..3

    unsigned long long acc[8][4];
    #pragma unroll
    for (int rr = 0; rr < 8; rr++)
        #pragma unroll
        for (int p = 0; p < 4; p++) acc[rr][p] = 0ull;

    float4 s1a = make_float4(0.f, 0.f, 0.f, 0.f);
    float4 s1b = make_float4(0.f, 0.f, 0.f, 0.f);

    const unsigned sxb = (unsigned)__cvta_generic_to_shared(sx);
    const unsigned rbase = sxb + ig * 4 * 144 + rt * 32;   // row-oct addr
    const unsigned cbase = sxb + ig * 4 * 144 + ct * 32;   // col-oct addr

    // prefetch tile 0
    float4 n0, n1; float wn;
    {
        const float4* vp = (const float4*)g_V + (size_t)(i0base + ii_s) * 8;
        n0 = vp[cc_s]; n1 = vp[cc_s + 4]; wn = sw[ii_s];
    }

    for (int tile = 0; tile < CHUNK / 32; tile++) {
        // ---- stage x = sqrt(w) * v ; accumulate S1 contribution w*v
        {
            float4 x0, x1;
            x0.x = wn * n0.x; x0.y = wn * n0.y; x0.z = wn * n0.z; x0.w = wn * n0.w;
            x1.x = wn * n1.x; x1.y = wn * n1.y; x1.z = wn * n1.z; x1.w = wn * n1.w;
            s1a.x += wn * x0.x; s1a.y += wn * x0.y;
            s1a.z += wn * x0.z; s1a.w += wn * x0.w;
            s1b.x += wn * x1.x; s1b.y += wn * x1.y;
            s1b.z += wn * x1.z; s1b.w += wn * x1.w;
            *(float4*)(sx + ii_s * 36 + cc_s * 4)      = x0;
            *(float4*)(sx + ii_s * 36 + 16 + cc_s * 4) = x1;
        }
        __syncthreads();

        // prefetch next tile (L2 latency hides under the FMA loop)
        if (tile < CHUNK / 32 - 1) {
            const int iloc = (tile + 1) * 32 + ii_s;
            const float4* vp = (const float4*)g_V + (size_t)(i0base + iloc) * 8;
            n0 = vp[cc_s]; n1 = vp[cc_s + 4]; wn = sw[iloc];
        }

        // ---- 8x8 outer-product accumulation over this thread's 4 ii's
        #pragma unroll
        for (int k = 0; k < 4; k++) {
            const unsigned ro = rbase + k * 144;
            const unsigned co = cbase + k * 144;
            float r0, r1, r2, r3, r4_, r5, r6, r7;
            asm volatile("ld.shared.v4.f32 {%0,%1,%2,%3}, [%4];"
                         : "=f"(r0), "=f"(r1), "=f"(r2), "=f"(r3) : "r"(ro));
            asm volatile("ld.shared.v4.f32 {%0,%1,%2,%3}, [%4];"
                         : "=f"(r4_), "=f"(r5), "=f"(r6), "=f"(r7)
                         : "r"(ro + 16));
            unsigned long long c01, c23, c45, c67;
            asm volatile("ld.shared.v2.b64 {%0,%1}, [%2];"
                         : "=l"(c01), "=l"(c23) : "r"(co));
            asm volatile("ld.shared.v2.b64 {%0,%1}, [%2];"
                         : "=l"(c45), "=l"(c67) : "r"(co + 16));
            unsigned long long d;
            #define ROW_FMA(RR, RV)                                          \
                asm("mov.b64 %0, {%1,%1};" : "=l"(d) : "f"(RV));             \
                asm("fma.rn.f32x2 %0, %1, %2, %0;" : "+l"(acc[RR][0])        \
                    : "l"(d), "l"(c01));                                     \
                asm("fma.rn.f32x2 %0, %1, %2, %0;" : "+l"(acc[RR][1])        \
                    : "l"(d), "l"(c23));                                     \
                asm("fma.rn.f32x2 %0, %1, %2, %0;" : "+l"(acc[RR][2])        \
                    : "l"(d), "l"(c45));                                     \
                asm("fma.rn.f32x2 %0, %1, %2, %0;" : "+l"(acc[RR][3])        \
                    : "l"(d), "l"(c67));
            ROW_FMA(0, r0) ROW_FMA(1, r1) ROW_FMA(2, r2) ROW_FMA(3, r3)
            ROW_FMA(4, r4_) ROW_FMA(5, r5) ROW_FMA(6, r6) ROW_FMA(7, r7)
            #undef ROW_FMA
        }
        __syncthreads();
    }

    // ---- S1: dump per-thread partials into sx (free now), reduce over ii
    *(float4*)(sx + ii_s * 36 + cc_s * 4)      = s1a;
    *(float4*)(sx + ii_s * 36 + 16 + cc_s * 4) = s1b;
    __syncthreads();
    if (t < 32) {
        float ssum = 0.f;
        #pragma unroll
        for (int ii = 0; ii < 32; ii++) ssum += sx[ii * 36 + t];
        g_partS1[((size_t)a * NS + s) * KK + t] = ssum;
    }

    // ---- S2: reduce 8 ig-partials per output through smem, 8 rounds.
    float* p2base = g_partS2 + ((size_t)a * NS + s) * (KK * KK);
    #pragma unroll
    for (int rg = 0; rg < 8; rg++) {
        __syncthreads();
        float p0, p1, p2, p3, p4, p5, p6, p7;
        asm("mov.b64 {%0,%1}, %2;" : "=f"(p0), "=f"(p1) : "l"(acc[rg][0]));
        asm("mov.b64 {%0,%1}, %2;" : "=f"(p2), "=f"(p3) : "l"(acc[rg][1]));
        asm("mov.b64 {%0,%1}, %2;" : "=f"(p4), "=f"(p5) : "l"(acc[rg][2]));
        asm("mov.b64 {%0,%1}, %2;" : "=f"(p6), "=f"(p7) : "l"(acc[rg][3]));
        float* dst = sx + ig * 132 + tl * 8;
        *(float4*)dst       = make_float4(p0, p1, p2, p3);
        *(float4*)(dst + 4) = make_float4(p4, p5, p6, p7);
        __syncthreads();
        float ssum = 0.f;
        #pragma unroll
        for (int g = 0; g < 8; g++) ssum += sx[g * 132 + t];
        const int R = (t >> 5) * 8 + rg;
        const int C = ((t >> 3) & 3) * 8 + (t & 7);
        p2base[R * KK + C] = ssum;
    }
}

// ---------------------------------------------------------------------------
// Kernel 3a: psi partials. grid (128 clusters x 4 slices), 256 threads.
// ---------------------------------------------------------------------------
__global__ void finalize_part_kernel(void)
{
    const int a = blockIdx.x;
    const int y = blockIdx.y;
    const int t = threadIdx.x;    // 0..255
    __shared__ float op[32 * 33];
    __shared__ float vbar[32];
    __shared__ float zs;
    __shared__ float red[8];

    {
        const float4 s = g_OP4[a * 256 + t];
        const int e = t * 4;
        const int r = e >> 5, c = e & 31;
        op[r * 33 + c + 0] = s.x;
        op[r * 33 + c + 1] = s.y;
        op[r * 33 + c + 2] = s.z;
        op[r * 33 + c + 3] = s.w;
    }
    if (t == 0) {
        float Z = 0.f;
        #pragma unroll
        for (int ss = 0; ss < NS; ss++) Z += g_partZ[a * NS + ss];
        zs = (Z > 0.f) ? Z : 1.0f;
    }
    if (t < KK) {
        float s1 = 0.f;
        #pragma unroll
        for (int ss = 0; ss < NS; ss++)
            s1 += g_partS1[(a * NS + ss) * KK + t];
        vbar[t] = s1;
    }
    __syncthreads();
    const float Zs = zs;
    if (t < KK) vbar[t] = vbar[t] / Zs;
    __syncthreads();

    const int e = y * 256 + t;
    const int l = e >> 5, m = e & 31;
    float s2 = 0.f;
    #pragma unroll
    for (int ss = 0; ss < NS; ss++)
        s2 += g_partS2[((size_t)a * NS + ss) * (KK * KK) + e];
    const float C = s2 / Zs - vbar[l] * vbar[m];
    float S = 0.f;
    #pragma unroll
    for (int k = 0; k < KK; k++)
        S += op[k * 33 + l] * op[k * 33 + m];
    float psi = S * C;

    #pragma unroll
    for (int off = 16; off; off >>= 1)
        psi += __shfl_xor_sync(0xffffffffu, psi, off);
    if ((t & 31) == 0) red[t >> 5] = psi;
    __syncthreads();
    if (t == 0) {
        float tot = 0.f;
        #pragma unroll
        for (int ww = 0; ww < 8; ww++) tot += red[ww];
        g_psiPart[a * 4 + y] = tot;
    }
}

// ---------------------------------------------------------------------------
// Kernel 3b: combine. One block of 128 threads; thread a -> out[a].
// ---------------------------------------------------------------------------
__global__ void finalize_combine_kernel(float* __restrict__ out)
{
    const int a = threadIdx.x;
    float cnt = 0.f;
    #pragma unroll
    for (int ss = 0; ss < NS; ss++) cnt += g_partCnt[a * NS + ss];
    const float p = g_psiPart[a * 4 + 0] + g_psiPart[a * 4 + 1]
                  + g_psiPart[a * 4 + 2] + g_psiPart[a * 4 + 3];
    out[a] = (cnt >= 2.0f) ? p : 0.0f;
}

// ---------------------------------------------------------------------------
// R13 schedule (116.3us measured): side stream hides wreduce + reduce_op
// under solve; join before accum. solve is the 4th launch for ncu.
// ---------------------------------------------------------------------------
extern "C" void kernel_launch(void* const* d_in, const int* in_sizes, int n_in,
                              void* d_out, int out_size)
{
    const float* W  = (const float*)d_in[0];   // (N, M, G)
    const float* mu = (const float*)d_in[1];   // (N, G, K)
    const float* oc = (const float*)d_in[2];   // (N, G, K, K)
    const float* op = (const float*)d_in[3];   // (M, G, K, K)
    float* out = (float*)d_out;                // (M,)

    // fork
    cudaEventRecord(g_hx.evRoot, 0);
    cudaStreamWaitEvent(g_hx.side, g_hx.evRoot, 0);

    // side stream: W reduce + omega_parent reduce (hidden under solve)
    wreduce_kernel<<<NN / 32, 256, 0, g_hx.side>>>(W);
    reduce_op_kernel<<<MM / 2, 256, 0, g_hx.side>>>((const float4*)op, 0);
    reduce_op_kernel<<<MM / 2, 256, 0, g_hx.side>>>((const float4*)op, MM / 2);

    // main stream: pipelined 2-system solve (4th launch -> ncu target)
    solve_kernel<<<NN / 2, 128>>>(oc, mu);

    // join
    cudaEventRecord(g_hx.evSide, g_hx.side);
    cudaStreamWaitEvent(0, g_hx.evSide, 0);

    accum_kernel<<<dim3(MM, NS), 128>>>();
    finalize_part_kernel<<<dim3(MM, 4), 256>>>();
    finalize_combine_kernel<<<1, MM>>>(out);
}

// round 16
// speedup vs baseline: 1.1234x; 1.1234x over previous
#include <cuda_runtime.h>

#define NN 4096
#define MM 128
#define KK 32
#define GG 16
#define NS 8
#define CHUNK (NN / NS)   // 512

// Scratch (device globals: no runtime allocation allowed)
__device__ float  g_V[NN * KK];                // transported-solve vectors v_i
__device__ float  g_wmT[MM * NN];              // masked mean weights, [a][i]
__device__ float4 g_OP4[MM * 256];             // pre-reduced omega_parent mean
__device__ float  g_partZ[MM * NS];
__device__ float  g_partCnt[MM * NS];
__device__ float  g_partS1[MM * NS * KK];
__device__ float  g_partS2[MM * NS * KK * KK];
__device__ float  g_psiPart[MM * 4];

// Lower-triangle float4-quad offsets (off = row*8 + quad), row-major.
// 144 entries; decode r = off>>3, c = (off&7)*4.
__constant__ unsigned char c_tri[144] = {
      0,   8,  16,  24,
     32,  33,  40,  41,  48,  49,  56,  57,
     64,  65,  66,  72,  73,  74,  80,  81,  82,  88,  89,  90,
     96,  97,  98,  99, 104, 105, 106, 107, 112, 113, 114, 115,
    120, 121, 122, 123,
    128, 129, 130, 131, 132, 136, 137, 138, 139, 140,
    144, 145, 146, 147, 148, 152, 153, 154, 155, 156,
    160, 161, 162, 163, 164, 165, 168, 169, 170, 171, 172, 173,
    176, 177, 178, 179, 180, 181, 184, 185, 186, 187, 188, 189,
    192, 193, 194, 195, 196, 197, 198, 200, 201, 202, 203, 204,
    205, 206, 208, 209, 210, 211, 212, 213, 214, 216, 217, 218,
    219, 220, 221, 222,
    224, 225, 226, 227, 228, 229, 230, 231, 232, 233, 234, 235,
    236, 237, 238, 239, 240, 241, 242, 243, 244, 245, 246, 247,
    248, 249, 250, 251, 252, 253, 254, 255
};

// Host-side stream/event plumbing (created once at load; NOT device memory).
struct HxStreams {
    cudaStream_t side;
    cudaEvent_t evRoot, evSide;
    HxStreams() {
        cudaStreamCreateWithFlags(&side, cudaStreamNonBlocking);
        cudaEventCreateWithFlags(&evRoot, cudaEventDisableTiming);
        cudaEventCreateWithFlags(&evSide, cudaEventDisableTiming);
    }
};
static HxStreams g_hx;

// ---------------------------------------------------------------------------
// Kernel 0: coalesced W reduce + mask + TRANSPOSE -> g_wmT[a][i].
// ---------------------------------------------------------------------------
__global__ void wreduce_kernel(const float* __restrict__ W)
{
    __shared__ float tile[32][129];
    const int i0 = blockIdx.x * 32;
    const int t = threadIdx.x;            // 0..255
    const int il = t >> 3;                // 0..31
    const int sub = t & 7;                // 0..7 -> a range sub*16..+15

    const float4* p = (const float4*)W + (size_t)(i0 + il) * 512 + sub * 64;
    #pragma unroll
    for (int aa = 0; aa < 16; aa++) {
        const float4 a0 = p[aa * 4 + 0];
        const float4 a1 = p[aa * 4 + 1];
        const float4 a2 = p[aa * 4 + 2];
        const float4 a3 = p[aa * 4 + 3];
        const float sum = (a0.x + a0.y + a0.z + a0.w)
                        + (a1.x + a1.y + a1.z + a1.w)
                        + (a2.x + a2.y + a2.z + a2.w)
                        + (a3.x + a3.y + a3.z + a3.w);
        const float wm = sum * 0.0625f;
        tile[il][sub * 16 + aa] = (wm >= 1e-6f) ? wm : 0.0f;
    }
    __syncthreads();

    const int a = t >> 1, hf = t & 1;
    float4 o0, o1, o2, o3;
    o0.x = tile[hf * 16 +  0][a]; o0.y = tile[hf * 16 +  1][a];
    o0.z = tile[hf * 16 +  2][a]; o0.w = tile[hf * 16 +  3][a];
    o1.x = tile[hf * 16 +  4][a]; o1.y = tile[hf * 16 +  5][a];
    o1.z = tile[hf * 16 +  6][a]; o1.w = tile[hf * 16 +  7][a];
    o2.x = tile[hf * 16 +  8][a]; o2.y = tile[hf * 16 +  9][a];
    o2.z = tile[hf * 16 + 10][a]; o2.w = tile[hf * 16 + 11][a];
    o3.x = tile[hf * 16 + 12][a]; o3.y = tile[hf * 16 + 13][a];
    o3.z = tile[hf * 16 + 14][a]; o3.w = tile[hf * 16 + 15][a];
    float4* dst = (float4*)(g_wmT + (size_t)a * NN + i0 + hf * 16);
    dst[0] = o0; dst[1] = o1; dst[2] = o2; dst[3] = o3;
}

// ---------------------------------------------------------------------------
// Kernel 1: fused reduce+solve, symmetry-halved loads v2.
// 160 threads: t<144 each load EXACTLY ONE lower-triangle quad (offset from
// the constant table -> no decode registers, fully uniform), reduce over G,
// store row quad + scalar-mirror sub-diagonal elements. Threads 144..159
// reduce the mu column (2 rows each). Elimination = R10 verbatim on t<128;
// warp 4 passes barriers. ~32 regs * 160 thr -> 12 blocks/SM = 94% occ.
// ---------------------------------------------------------------------------
__global__ void solve_kernel(const float* __restrict__ omega_child,
                             const float* __restrict__ mu_s)
{
    __shared__ float A[KK * 33];
    const int i = blockIdx.x;
    const int t = threadIdx.x;       // 0..159
    const int lane = t & 31, w = t >> 5;

    const float4* oc4 = (const float4*)(omega_child + (size_t)i * GG * KK * KK);

    if (t < 144) {
        const int off = c_tri[t];
        float4 s = oc4[off];
        #pragma unroll
        for (int g = 1; g < GG; g++) {
            const float4 v = oc4[g * 256 + off];
            s.x += v.x; s.y += v.y; s.z += v.z; s.w += v.w;
        }
        const int r = off >> 3;
        const int c = (off & 7) * 4;
        A[r * 33 + c + 0] = s.x;
        A[r * 33 + c + 1] = s.y;
        A[r * 33 + c + 2] = s.z;
        A[r * 33 + c + 3] = s.w;
        if (c + 0 < r) A[(c + 0) * 33 + r] = s.x;
        if (c + 1 < r) A[(c + 1) * 33 + r] = s.y;
        if (c + 2 < r) A[(c + 2) * 33 + r] = s.z;
        if (c + 3 < r) A[(c + 3) * 33 + r] = s.w;
    } else {
        const float* mu = mu_s + (size_t)i * GG * KK;
        const int t2 = t - 144;
        #pragma unroll
        for (int h = 0; h < 2; h++) {
            const int rr = t2 + h * 16;
            float s = 0.f;
            #pragma unroll
            for (int g = 0; g < GG; g++) s += mu[g * KK + rr];
            A[rr * 33 + 32] = s;
        }
    }
    __syncthreads();

    // Forward elimination (SPD: no pivoting) — R10 verbatim on t<128.
    for (int k = 0; k < KK - 1; k++) {
        if (t < 128) {
            const float invp = 1.0f / A[k * 33 + k];
            const int c = k + 1 + lane;
            for (int r = k + 1 + w; r < KK; r += 4) {
                const float m = A[r * 33 + k] * invp;
                if (c <= 32) A[r * 33 + c] -= m * A[k * 33 + c];
            }
        }
        __syncthreads();
    }

    // Backward Jordan on the b column only.
    for (int k = KK - 1; k >= 1; k--) {
        if (t < k) {
            const float xk = A[k * 33 + 32] / A[k * 33 + k];
            A[t * 33 + 32] -= A[t * 33 + k] * xk;
        }
        __syncthreads();
    }
    if (t < KK)
        g_V[(size_t)i * KK + t] = A[t * 33 + 32] / A[t * 33 + t];
}

// ---------------------------------------------------------------------------
// Kernel 1b: streaming mean of omega_parent over G -> g_OP4 (two halves so
// solve lands 4th for ncu).
// ---------------------------------------------------------------------------
__global__ void reduce_op_kernel(const float4* __restrict__ op4, int abase)
{
    const int gid = blockIdx.x * blockDim.x + threadIdx.x;
    const int a = abase + (gid >> 8);
    const int q = gid & 255;
    const float4* p = op4 + (size_t)a * (GG * 256) + q;
    float4 s0 = p[0];
    float4 s1 = p[256];
    #pragma unroll
    for (int g = 2; g < GG; g += 2) {
        const float4 va = p[g * 256];
        const float4 vb = p[(g + 1) * 256];
        s0.x += va.x; s0.y += va.y; s0.z += va.z; s0.w += va.w;
        s1.x += vb.x; s1.y += vb.y; s1.z += vb.z; s1.w += vb.w;
    }
    const float inv = 1.0f / 16.0f;
    s0.x = (s0.x + s1.x) * inv; s0.y = (s0.y + s1.y) * inv;
    s0.z = (s0.z + s1.z) * inv; s0.w = (s0.w + s1.w) * inv;
    g_OP4[a * 256 + q] = s0;
}

// ---------------------------------------------------------------------------
// Kernel 2: 8x8 register tile accum — R8/R10 VERBATIM (35.3us measured).
// FROZEN.
// ---------------------------------------------------------------------------
__global__ void __launch_bounds__(128, 3)
accum_kernel(void)
{
    const int a = blockIdx.x;
    const int s = blockIdx.y;
    const int t = threadIdx.x;     // 0..127
    const int i0base = s * CHUNK;

    __shared__ float sw[CHUNK];          // sqrt of masked mean weights (2 KB)
    __shared__ float sx[32 * 36];        // sqrt(w)*v tile, row stride 36
    __shared__ float zred[4], cred[4];

    // ---- Phase 0: coalesced wmT read (4 i's per thread)
    {
        const float4 wv =
            ((const float4*)(g_wmT + (size_t)a * NN + i0base))[t];
        float accZ = wv.x + wv.y + wv.z + wv.w;
        float accCnt = (wv.x > 0.f ? 1.f : 0.f) + (wv.y > 0.f ? 1.f : 0.f)
                     + (wv.z > 0.f ? 1.f : 0.f) + (wv.w > 0.f ? 1.f : 0.f);
        sw[4 * t + 0] = sqrtf(wv.x);
        sw[4 * t + 1] = sqrtf(wv.y);
        sw[4 * t + 2] = sqrtf(wv.z);
        sw[4 * t + 3] = sqrtf(wv.w);
        #pragma unroll
        for (int off = 16; off; off >>= 1) {
            accZ   += __shfl_xor_sync(0xffffffffu, accZ, off);
            accCnt += __shfl_xor_sync(0xffffffffu, accCnt, off);
        }
        if ((t & 31) == 0) { zred[t >> 5] = accZ; cred[t >> 5] = accCnt; }
    }
    __syncthreads();
    if (t == 0) {
        g_partZ[a * NS + s]   = zred[0] + zred[1] + zred[2] + zred[3];
        g_partCnt[a * NS + s] = cred[0] + cred[1] + cred[2] + cred[3];
    }

    const int ig = t >> 4;      // ii-group 0..7
    const int tl = t & 15;
    const int rt = tl >> 2;     // row-oct
    const int ct = tl & 3;      // col-oct
    const int ii_s = t >> 2;    // staging row 0..31
    const int cc_s = t & 3;     // staging quad 0..3

    unsigned long long acc[8][4];
    #pragma unroll
    for (int rr = 0; rr < 8; rr++)
        #pragma unroll
        for (int p = 0; p < 4; p++) acc[rr][p] = 0ull;

    float4 s1a = make_float4(0.f, 0.f, 0.f, 0.f);
    float4 s1b = make_float4(0.f, 0.f, 0.f, 0.f);

    const unsigned sxb = (unsigned)__cvta_generic_to_shared(sx);
    const unsigned rbase = sxb + ig * 4 * 144 + rt * 32;   // row-oct addr
    const unsigned cbase = sxb + ig * 4 * 144 + ct * 32;   // col-oct addr

    // prefetch tile 0
    float4 n0, n1; float wn;
    {
        const float4* vp = (const float4*)g_V + (size_t)(i0base + ii_s) * 8;
        n0 = vp[cc_s]; n1 = vp[cc_s + 4]; wn = sw[ii_s];
    }

    for (int tile = 0; tile < CHUNK / 32; tile++) {
        // ---- stage x = sqrt(w) * v ; accumulate S1 contribution w*v
        {
            float4 x0, x1;
            x0.x = wn * n0.x; x0.y = wn * n0.y; x0.z = wn * n0.z; x0.w = wn * n0.w;
            x1.x = wn * n1.x; x1.y = wn * n1.y; x1.z = wn * n1.z; x1.w = wn * n1.w;
            s1a.x += wn * x0.x; s1a.y += wn * x0.y;
            s1a.z += wn * x0.z; s1a.w += wn * x0.w;
            s1b.x += wn * x1.x; s1b.y += wn * x1.y;
            s1b.z += wn * x1.z; s1b.w += wn * x1.w;
            *(float4*)(sx + ii_s * 36 + cc_s * 4)      = x0;
            *(float4*)(sx + ii_s * 36 + 16 + cc_s * 4) = x1;
        }
        __syncthreads();

        // prefetch next tile (L2 latency hides under the FMA loop)
        if (tile < CHUNK / 32 - 1) {
            const int iloc = (tile + 1) * 32 + ii_s;
            const float4* vp = (const float4*)g_V + (size_t)(i0base + iloc) * 8;
            n0 = vp[cc_s]; n1 = vp[cc_s + 4]; wn = sw[iloc];
        }

        // ---- 8x8 outer-product accumulation over this thread's 4 ii's
        #pragma unroll
        for (int k = 0; k < 4; k++) {
            const unsigned ro = rbase + k * 144;
            const unsigned co = cbase + k * 144;
            float r0, r1, r2, r3, r4_, r5, r6, r7;
            asm volatile("ld.shared.v4.f32 {%0,%1,%2,%3}, [%4];"
                         : "=f"(r0), "=f"(r1), "=f"(r2), "=f"(r3) : "r"(ro));
            asm volatile("ld.shared.v4.f32 {%0,%1,%2,%3}, [%4];"
                         : "=f"(r4_), "=f"(r5), "=f"(r6), "=f"(r7)
                         : "r"(ro + 16));
            unsigned long long c01, c23, c45, c67;
            asm volatile("ld.shared.v2.b64 {%0,%1}, [%2];"
                         : "=l"(c01), "=l"(c23) : "r"(co));
            asm volatile("ld.shared.v2.b64 {%0,%1}, [%2];"
                         : "=l"(c45), "=l"(c67) : "r"(co + 16));
            unsigned long long d;
            #define ROW_FMA(RR, RV)                                          \
                asm("mov.b64 %0, {%1,%1};" : "=l"(d) : "f"(RV));             \
                asm("fma.rn.f32x2 %0, %1, %2, %0;" : "+l"(acc[RR][0])        \
                    : "l"(d), "l"(c01));                                     \
                asm("fma.rn.f32x2 %0, %1, %2, %0;" : "+l"(acc[RR][1])        \
                    : "l"(d), "l"(c23));                                     \
                asm("fma.rn.f32x2 %0, %1, %2, %0;" : "+l"(acc[RR][2])        \
                    : "l"(d), "l"(c45));                                     \
                asm("fma.rn.f32x2 %0, %1, %2, %0;" : "+l"(acc[RR][3])        \
                    : "l"(d), "l"(c67));
            ROW_FMA(0, r0) ROW_FMA(1, r1) ROW_FMA(2, r2) ROW_FMA(3, r3)
            ROW_FMA(4, r4_) ROW_FMA(5, r5) ROW_FMA(6, r6) ROW_FMA(7, r7)
            #undef ROW_FMA
        }
        __syncthreads();
    }

    // ---- S1: dump per-thread partials into sx (free now), reduce over ii
    *(float4*)(sx + ii_s * 36 + cc_s * 4)      = s1a;
    *(float4*)(sx + ii_s * 36 + 16 + cc_s * 4) = s1b;
    __syncthreads();
    if (t < 32) {
        float ssum = 0.f;
        #pragma unroll
        for (int ii = 0; ii < 32; ii++) ssum += sx[ii * 36 + t];
        g_partS1[((size_t)a * NS + s) * KK + t] = ssum;
    }

    // ---- S2: reduce 8 ig-partials per output through smem, 8 rounds.
    float* p2base = g_partS2 + ((size_t)a * NS + s) * (KK * KK);
    #pragma unroll
    for (int rg = 0; rg < 8; rg++) {
        __syncthreads();
        float p0, p1, p2, p3, p4, p5, p6, p7;
        asm("mov.b64 {%0,%1}, %2;" : "=f"(p0), "=f"(p1) : "l"(acc[rg][0]));
        asm("mov.b64 {%0,%1}, %2;" : "=f"(p2), "=f"(p3) : "l"(acc[rg][1]));
        asm("mov.b64 {%0,%1}, %2;" : "=f"(p4), "=f"(p5) : "l"(acc[rg][2]));
        asm("mov.b64 {%0,%1}, %2;" : "=f"(p6), "=f"(p7) : "l"(acc[rg][3]));
        float* dst = sx + ig * 132 + tl * 8;
        *(float4*)dst       = make_float4(p0, p1, p2, p3);
        *(float4*)(dst + 4) = make_float4(p4, p5, p6, p7);
        __syncthreads();
        float ssum = 0.f;
        #pragma unroll
        for (int g = 0; g < 8; g++) ssum += sx[g * 132 + t];
        const int R = (t >> 5) * 8 + rg;
        const int C = ((t >> 3) & 3) * 8 + (t & 7);
        p2base[R * KK + C] = ssum;
    }
}

// ---------------------------------------------------------------------------
// Kernel 3a: psi partials. grid (128 clusters x 4 slices), 256 threads.
// ---------------------------------------------------------------------------
__global__ void finalize_part_kernel(void)
{
    const int a = blockIdx.x;
    const int y = blockIdx.y;
    const int t = threadIdx.x;    // 0..255
    __shared__ float op[32 * 33];
    __shared__ float vbar[32];
    __shared__ float zs;
    __shared__ float red[8];

    {
        const float4 s = g_OP4[a * 256 + t];
        const int e = t * 4;
        const int r = e >> 5, c = e & 31;
        op[r * 33 + c + 0] = s.x;
        op[r * 33 + c + 1] = s.y;
        op[r * 33 + c + 2] = s.z;
        op[r * 33 + c + 3] = s.w;
    }
    if (t == 0) {
        float Z = 0.f;
        #pragma unroll
        for (int ss = 0; ss < NS; ss++) Z += g_partZ[a * NS + ss];
        zs = (Z > 0.f) ? Z : 1.0f;
    }
    if (t < KK) {
        float s1 = 0.f;
        #pragma unroll
        for (int ss = 0; ss < NS; ss++)
            s1 += g_partS1[(a * NS + ss) * KK + t];
        vbar[t] = s1;
    }
    __syncthreads();
    const float Zs = zs;
    if (t < KK) vbar[t] = vbar[t] / Zs;
    __syncthreads();

    const int e = y * 256 + t;
    const int l = e >> 5, m = e & 31;
    float s2 = 0.f;
    #pragma unroll
    for (int ss = 0; ss < NS; ss++)
        s2 += g_partS2[((size_t)a * NS + ss) * (KK * KK) + e];
    const float C = s2 / Zs - vbar[l] * vbar[m];
    float S = 0.f;
    #pragma unroll
    for (int k = 0; k < KK; k++)
        S += op[k * 33 + l] * op[k * 33 + m];
    float psi = S * C;

    #pragma unroll
    for (int off = 16; off; off >>= 1)
        psi += __shfl_xor_sync(0xffffffffu, psi, off);
    if ((t & 31) == 0) red[t >> 5] = psi;
    __syncthreads();
    if (t == 0) {
        float tot = 0.f;
        #pragma unroll
        for (int ww = 0; ww < 8; ww++) tot += red[ww];
        g_psiPart[a * 4 + y] = tot;
    }
}

// ---------------------------------------------------------------------------
// Kernel 3b: combine. One block of 128 threads; thread a -> out[a].
// ---------------------------------------------------------------------------
__global__ void finalize_combine_kernel(float* __restrict__ out)
{
    const int a = threadIdx.x;
    float cnt = 0.f;
    #pragma unroll
    for (int ss = 0; ss < NS; ss++) cnt += g_partCnt[a * NS + ss];
    const float p = g_psiPart[a * 4 + 0] + g_psiPart[a * 4 + 1]
                  + g_psiPart[a * 4 + 2] + g_psiPart[a * 4 + 3];
    out[a] = (cnt >= 2.0f) ? p : 0.0f;
}

// ---------------------------------------------------------------------------
// R13 schedule: side stream hides wreduce + reduce_op under solve; join
// before accum. solve is the 4th launch for ncu.
// ---------------------------------------------------------------------------
extern "C" void kernel_launch(void* const* d_in, const int* in_sizes, int n_in,
                              void* d_out, int out_size)
{
    const float* W  = (const float*)d_in[0];   // (N, M, G)
    const float* mu = (const float*)d_in[1];   // (N, G, K)
    const float* oc = (const float*)d_in[2];   // (N, G, K, K)
    const float* op = (const float*)d_in[3];   // (M, G, K, K)
    float* out = (float*)d_out;                // (M,)

    // fork
    cudaEventRecord(g_hx.evRoot, 0);
    cudaStreamWaitEvent(g_hx.side, g_hx.evRoot, 0);

    // side stream: W reduce + omega_parent reduce (hidden under solve)
    wreduce_kernel<<<NN / 32, 256, 0, g_hx.side>>>(W);
    reduce_op_kernel<<<MM / 2, 256, 0, g_hx.side>>>((const float4*)op, 0);
    reduce_op_kernel<<<MM / 2, 256, 0, g_hx.side>>>((const float4*)op, MM / 2);

    // main stream: symmetry-halved solve (4th launch -> ncu target)
    solve_kernel<<<NN, 160>>>(oc, mu);

    // join
    cudaEventRecord(g_hx.evSide, g_hx.side);
    cudaStreamWaitEvent(0, g_hx.evSide, 0);

    accum_kernel<<<dim3(MM, NS), 128>>>();
    finalize_part_kernel<<<dim3(MM, 4), 256>>>();
    finalize_combine_kernel<<<1, MM>>>(out);
}

// round 17
// speedup vs baseline: 1.1757x; 1.0465x over previous
#include <cuda_runtime.h>

#define NN 4096
#define MM 128
#define KK 32
#define GG 16
#define NS 8
#define CHUNK (NN / NS)   // 512

// Scratch (device globals: no runtime allocation allowed)
__device__ float  g_V[NN * KK];                // transported-solve vectors v_i
__device__ float  g_wmT[MM * NN];              // masked mean weights, [a][i]
__device__ float4 g_OP4[MM * 256];             // pre-reduced omega_parent mean
__device__ float  g_S[MM * KK * KK];           // S = op_avg^T op_avg (512 KB)
__device__ float  g_partZ[MM * NS];
__device__ float  g_partCnt[MM * NS];
__device__ float  g_partS1[MM * NS * KK];
__device__ float  g_partS2[MM * NS * KK * KK];
__device__ float  g_psiPart[MM * 4];

// Host-side stream/event plumbing (created once at load; NOT device memory).
struct HxStreams {
    cudaStream_t side;
    cudaEvent_t evRoot, evSide;
    HxStreams() {
        cudaStreamCreateWithFlags(&side, cudaStreamNonBlocking);
        cudaEventCreateWithFlags(&evRoot, cudaEventDisableTiming);
        cudaEventCreateWithFlags(&evSide, cudaEventDisableTiming);
    }
};
static HxStreams g_hx;

// ---------------------------------------------------------------------------
// Kernel 0: coalesced W reduce + mask + TRANSPOSE -> g_wmT[a][i].
// ---------------------------------------------------------------------------
__global__ void wreduce_kernel(const float* __restrict__ W)
{
    __shared__ float tile[32][129];
    const int i0 = blockIdx.x * 32;
    const int t = threadIdx.x;            // 0..255
    const int il = t >> 3;                // 0..31
    const int sub = t & 7;                // 0..7 -> a range sub*16..+15

    const float4* p = (const float4*)W + (size_t)(i0 + il) * 512 + sub * 64;
    #pragma unroll
    for (int aa = 0; aa < 16; aa++) {
        const float4 a0 = p[aa * 4 + 0];
        const float4 a1 = p[aa * 4 + 1];
        const float4 a2 = p[aa * 4 + 2];
        const float4 a3 = p[aa * 4 + 3];
        const float sum = (a0.x + a0.y + a0.z + a0.w)
                        + (a1.x + a1.y + a1.z + a1.w)
                        + (a2.x + a2.y + a2.z + a2.w)
                        + (a3.x + a3.y + a3.z + a3.w);
        const float wm = sum * 0.0625f;
        tile[il][sub * 16 + aa] = (wm >= 1e-6f) ? wm : 0.0f;
    }
    __syncthreads();

    const int a = t >> 1, hf = t & 1;
    float4 o0, o1, o2, o3;
    o0.x = tile[hf * 16 +  0][a]; o0.y = tile[hf * 16 +  1][a];
    o0.z = tile[hf * 16 +  2][a]; o0.w = tile[hf * 16 +  3][a];
    o1.x = tile[hf * 16 +  4][a]; o1.y = tile[hf * 16 +  5][a];
    o1.z = tile[hf * 16 +  6][a]; o1.w = tile[hf * 16 +  7][a];
    o2.x = tile[hf * 16 +  8][a]; o2.y = tile[hf * 16 +  9][a];
    o2.z = tile[hf * 16 + 10][a]; o2.w = tile[hf * 16 + 11][a];
    o3.x = tile[hf * 16 + 12][a]; o3.y = tile[hf * 16 + 13][a];
    o3.z = tile[hf * 16 + 14][a]; o3.w = tile[hf * 16 + 15][a];
    float4* dst = (float4*)(g_wmT + (size_t)a * NN + i0 + hf * 16);
    dst[0] = o0; dst[1] = o1; dst[2] = o2; dst[3] = o3;
}

// ---------------------------------------------------------------------------
// Kernel 1: fused reduce+solve — R2/R10 design VERBATIM (73.3us measured,
// occ 86%, 3.84 TB/s). FROZEN: symmetry can't cut bytes (128B row = 1 line,
// every line touched), and every schedule/batching variant measured worse.
// ---------------------------------------------------------------------------
__global__ void solve_kernel(const float* __restrict__ omega_child,
                             const float* __restrict__ mu_s)
{
    __shared__ float A[KK * 33];
    const int i = blockIdx.x;
    const int t = threadIdx.x;       // 0..127
    const int lane = t & 31, w = t >> 5;

    const float4* oc4 = (const float4*)(omega_child + (size_t)i * GG * KK * KK);
    #pragma unroll
    for (int q = t; q < 256; q += 128) {
        float4 s = make_float4(0.f, 0.f, 0.f, 0.f);
        #pragma unroll
        for (int g = 0; g < GG; g++) {
            float4 v = oc4[g * 256 + q];
            s.x += v.x; s.y += v.y; s.z += v.z; s.w += v.w;
        }
        const int e = q * 4;
        const int r = e >> 5, c = e & 31;
        A[r * 33 + c + 0] = s.x;
        A[r * 33 + c + 1] = s.y;
        A[r * 33 + c + 2] = s.z;
        A[r * 33 + c + 3] = s.w;
    }
    if (t < KK) {
        const float* mu = mu_s + (size_t)i * GG * KK;
        float s = 0.f;
        #pragma unroll
        for (int g = 0; g < GG; g++) s += mu[g * KK + t];
        A[t * 33 + 32] = s;
    }
    __syncthreads();

    for (int k = 0; k < KK - 1; k++) {
        const float invp = 1.0f / A[k * 33 + k];
        const int c = k + 1 + lane;
        for (int r = k + 1 + w; r < KK; r += 4) {
            const float m = A[r * 33 + k] * invp;
            if (c <= 32) A[r * 33 + c] -= m * A[k * 33 + c];
        }
        __syncthreads();
    }

    for (int k = KK - 1; k >= 1; k--) {
        if (t < k) {
            const float xk = A[k * 33 + 32] / A[k * 33 + k];
            A[t * 33 + 32] -= A[t * 33 + k] * xk;
        }
        __syncthreads();
    }
    if (t < KK)
        g_V[(size_t)i * KK + t] = A[t * 33 + 32] / A[t * 33 + t];
}

// ---------------------------------------------------------------------------
// Kernel 1b: streaming mean of omega_parent over G -> g_OP4.
// ---------------------------------------------------------------------------
__global__ void reduce_op_kernel(const float4* __restrict__ op4)
{
    const int gid = blockIdx.x * blockDim.x + threadIdx.x;  // 0..32767
    const int a = gid >> 8;
    const int q = gid & 255;
    const float4* p = op4 + (size_t)a * (GG * 256) + q;
    float4 s0 = p[0];
    float4 s1 = p[256];
    #pragma unroll
    for (int g = 2; g < GG; g += 2) {
        const float4 va = p[g * 256];
        const float4 vb = p[(g + 1) * 256];
        s0.x += va.x; s0.y += va.y; s0.z += va.z; s0.w += va.w;
        s1.x += vb.x; s1.y += vb.y; s1.z += vb.z; s1.w += vb.w;
    }
    const float inv = 1.0f / 16.0f;
    s0.x = (s0.x + s1.x) * inv; s0.y = (s0.y + s1.y) * inv;
    s0.z = (s0.z + s1.z) * inv; s0.w = (s0.w + s1.w) * inv;
    g_OP4[gid] = s0;
}

// ---------------------------------------------------------------------------
// Kernel 1c: S[a] = op_avg^T op_avg, hoisted out of finalize (hidden on the
// side stream under solve). One block per a; thread t -> 4 (l,m) entries.
// ---------------------------------------------------------------------------
__global__ void computeS_kernel(void)
{
    const int a = blockIdx.x;
    const int t = threadIdx.x;    // 0..255
    __shared__ float op[32 * 33];

    {
        const float4 s = g_OP4[a * 256 + t];
        const int e = t * 4;
        const int r = e >> 5, c = e & 31;
        op[r * 33 + c + 0] = s.x;
        op[r * 33 + c + 1] = s.y;
        op[r * 33 + c + 2] = s.z;
        op[r * 33 + c + 3] = s.w;
    }
    __syncthreads();

    float* Sout = g_S + (size_t)a * (KK * KK);
    #pragma unroll
    for (int j = 0; j < 4; j++) {
        const int e = t + 256 * j;
        const int l = e >> 5, m = e & 31;
        float S = 0.f;
        #pragma unroll
        for (int k = 0; k < KK; k++)
            S += op[k * 33 + l] * op[k * 33 + m];
        Sout[e] = S;
    }
}

// ---------------------------------------------------------------------------
// Kernel 2: 8x8 register tile accum — R8/R10 VERBATIM (35.3us measured).
// FROZEN.
// ---------------------------------------------------------------------------
__global__ void __launch_bounds__(128, 3)
accum_kernel(void)
{
    const int a = blockIdx.x;
    const int s = blockIdx.y;
    const int t = threadIdx.x;     // 0..127
    const int i0base = s * CHUNK;

    __shared__ float sw[CHUNK];          // sqrt of masked mean weights (2 KB)
    __shared__ float sx[32 * 36];        // sqrt(w)*v tile, row stride 36
    __shared__ float zred[4], cred[4];

    // ---- Phase 0: coalesced wmT read (4 i's per thread)
    {
        const float4 wv =
            ((const float4*)(g_wmT + (size_t)a * NN + i0base))[t];
        float accZ = wv.x + wv.y + wv.z + wv.w;
        float accCnt = (wv.x > 0.f ? 1.f : 0.f) + (wv.y > 0.f ? 1.f : 0.f)
                     + (wv.z > 0.f ? 1.f : 0.f) + (wv.w > 0.f ? 1.f : 0.f);
        sw[4 * t + 0] = sqrtf(wv.x);
        sw[4 * t + 1] = sqrtf(wv.y);
        sw[4 * t + 2] = sqrtf(wv.z);
        sw[4 * t + 3] = sqrtf(wv.w);
        #pragma unroll
        for (int off = 16; off; off >>= 1) {
            accZ   += __shfl_xor_sync(0xffffffffu, accZ, off);
            accCnt += __shfl_xor_sync(0xffffffffu, accCnt, off);
        }
        if ((t & 31) == 0) { zred[t >> 5] = accZ; cred[t >> 5] = accCnt; }
    }
    __syncthreads();
    if (t == 0) {
        g_partZ[a * NS + s]   = zred[0] + zred[1] + zred[2] + zred[3];
        g_partCnt[a * NS + s] = cred[0] + cred[1] + cred[2] + cred[3];
    }

    const int ig = t >> 4;      // ii-group 0..7
    const int tl = t & 15;
    const int rt = tl >> 2;     // row-oct
    const int ct = tl & 3;      // col-oct
    const int ii_s = t >> 2;    // staging row 0..31
    const int cc_s = t & 3;     // staging quad 0..3

    unsigned long long acc[8][4];
    #pragma unroll
    for (int rr = 0; rr < 8; rr++)
        #pragma unroll
        for (int p = 0; p < 4; p++) acc[rr][p] = 0ull;

    float4 s1a = make_float4(0.f, 0.f, 0.f, 0.f);
    float4 s1b = make_float4(0.f, 0.f, 0.f, 0.f);

    const unsigned sxb = (unsigned)__cvta_generic_to_shared(sx);
    const unsigned rbase = sxb + ig * 4 * 144 + rt * 32;   // row-oct addr
    const unsigned cbase = sxb + ig * 4 * 144 + ct * 32;   // col-oct addr

    // prefetch tile 0
    float4 n0, n1; float wn;
    {
        const float4* vp = (const float4*)g_V + (size_t)(i0base + ii_s) * 8;
        n0 = vp[cc_s]; n1 = vp[cc_s + 4]; wn = sw[ii_s];
    }

    for (int tile = 0; tile < CHUNK / 32; tile++) {
        // ---- stage x = sqrt(w) * v ; accumulate S1 contribution w*v
        {
            float4 x0, x1;
            x0.x = wn * n0.x; x0.y = wn * n0.y; x0.z = wn * n0.z; x0.w = wn * n0.w;
            x1.x = wn * n1.x; x1.y = wn * n1.y; x1.z = wn * n1.z; x1.w = wn * n1.w;
            s1a.x += wn * x0.x; s1a.y += wn * x0.y;
            s1a.z += wn * x0.z; s1a.w += wn * x0.w;
            s1b.x += wn * x1.x; s1b.y += wn * x1.y;
            s1b.z += wn * x1.z; s1b.w += wn * x1.w;
            *(float4*)(sx + ii_s * 36 + cc_s * 4)      = x0;
            *(float4*)(sx + ii_s * 36 + 16 + cc_s * 4) = x1;
        }
        __syncthreads();

        // prefetch next tile (L2 latency hides under the FMA loop)
        if (tile < CHUNK / 32 - 1) {
            const int iloc = (tile + 1) * 32 + ii_s;
            const float4* vp = (const float4*)g_V + (size_t)(i0base + iloc) * 8;
            n0 = vp[cc_s]; n1 = vp[cc_s + 4]; wn = sw[iloc];
        }

        // ---- 8x8 outer-product accumulation over this thread's 4 ii's
        #pragma unroll
        for (int k = 0; k < 4; k++) {
            const unsigned ro = rbase + k * 144;
            const unsigned co = cbase + k * 144;
            float r0, r1, r2, r3, r4_, r5, r6, r7;
            asm volatile("ld.shared.v4.f32 {%0,%1,%2,%3}, [%4];"
                         : "=f"(r0), "=f"(r1), "=f"(r2), "=f"(r3) : "r"(ro));
            asm volatile("ld.shared.v4.f32 {%0,%1,%2,%3}, [%4];"
                         : "=f"(r4_), "=f"(r5), "=f"(r6), "=f"(r7)
                         : "r"(ro + 16));
            unsigned long long c01, c23, c45, c67;
            asm volatile("ld.shared.v2.b64 {%0,%1}, [%2];"
                         : "=l"(c01), "=l"(c23) : "r"(co));
            asm volatile("ld.shared.v2.b64 {%0,%1}, [%2];"
                         : "=l"(c45), "=l"(c67) : "r"(co + 16));
            unsigned long long d;
            #define ROW_FMA(RR, RV)                                          \
                asm("mov.b64 %0, {%1,%1};" : "=l"(d) : "f"(RV));             \
                asm("fma.rn.f32x2 %0, %1, %2, %0;" : "+l"(acc[RR][0])        \
                    : "l"(d), "l"(c01));                                     \
                asm("fma.rn.f32x2 %0, %1, %2, %0;" : "+l"(acc[RR][1])        \
                    : "l"(d), "l"(c23));                                     \
                asm("fma.rn.f32x2 %0, %1, %2, %0;" : "+l"(acc[RR][2])        \
                    : "l"(d), "l"(c45));                                     \
                asm("fma.rn.f32x2 %0, %1, %2, %0;" : "+l"(acc[RR][3])        \
                    : "l"(d), "l"(c67));
            ROW_FMA(0, r0) ROW_FMA(1, r1) ROW_FMA(2, r2) ROW_FMA(3, r3)
            ROW_FMA(4, r4_) ROW_FMA(5, r5) ROW_FMA(6, r6) ROW_FMA(7, r7)
            #undef ROW_FMA
        }
        __syncthreads();
    }

    // ---- S1: dump per-thread partials into sx (free now), reduce over ii
    *(float4*)(sx + ii_s * 36 + cc_s * 4)      = s1a;
    *(float4*)(sx + ii_s * 36 + 16 + cc_s * 4) = s1b;
    __syncthreads();
    if (t < 32) {
        float ssum = 0.f;
        #pragma unroll
        for (int ii = 0; ii < 32; ii++) ssum += sx[ii * 36 + t];
        g_partS1[((size_t)a * NS + s) * KK + t] = ssum;
    }

    // ---- S2: reduce 8 ig-partials per output through smem, 8 rounds.
    float* p2base = g_partS2 + ((size_t)a * NS + s) * (KK * KK);
    #pragma unroll
    for (int rg = 0; rg < 8; rg++) {
        __syncthreads();
        float p0, p1, p2, p3, p4, p5, p6, p7;
        asm("mov.b64 {%0,%1}, %2;" : "=f"(p0), "=f"(p1) : "l"(acc[rg][0]));
        asm("mov.b64 {%0,%1}, %2;" : "=f"(p2), "=f"(p3) : "l"(acc[rg][1]));
        asm("mov.b64 {%0,%1}, %2;" : "=f"(p4), "=f"(p5) : "l"(acc[rg][2]));
        asm("mov.b64 {%0,%1}, %2;" : "=f"(p6), "=f"(p7) : "l"(acc[rg][3]));
        float* dst = sx + ig * 132 + tl * 8;
        *(float4*)dst       = make_float4(p0, p1, p2, p3);
        *(float4*)(dst + 4) = make_float4(p4, p5, p6, p7);
        __syncthreads();
        float ssum = 0.f;
        #pragma unroll
        for (int g = 0; g < 8; g++) ssum += sx[g * 132 + t];
        const int R = (t >> 5) * 8 + rg;
        const int C = ((t >> 3) & 3) * 8 + (t & 7);
        p2base[R * KK + C] = ssum;
    }
}

// ---------------------------------------------------------------------------
// Kernel 3a: psi partials. grid (128 clusters x 4 slices), 256 threads.
// S is precomputed in g_S (computeS on the side stream) -> no k-loop here.
// ---------------------------------------------------------------------------
__global__ void finalize_part_kernel(void)
{
    const int a = blockIdx.x;
    const int y = blockIdx.y;
    const int t = threadIdx.x;    // 0..255
    __shared__ float vbar[32];
    __shared__ float zs;
    __shared__ float red[8];

    if (t == 0) {
        float Z = 0.f;
        #pragma unroll
        for (int ss = 0; ss < NS; ss++) Z += g_partZ[a * NS + ss];
        zs = (Z > 0.f) ? Z : 1.0f;
    }
    if (t >= 32 && t < 64) {
        float s1 = 0.f;
        #pragma unroll
        for (int ss = 0; ss < NS; ss++)
            s1 += g_partS1[(a * NS + ss) * KK + (t - 32)];
        vbar[t - 32] = s1;
    }
    __syncthreads();
    const float Zs = zs;
    if (t < KK) vbar[t] = vbar[t] / Zs;
    __syncthreads();

    const int e = y * 256 + t;
    const int l = e >> 5, m = e & 31;
    float s2 = 0.f;
    #pragma unroll
    for (int ss = 0; ss < NS; ss++)
        s2 += g_partS2[((size_t)a * NS + ss) * (KK * KK) + e];
    const float C = s2 / Zs - vbar[l] * vbar[m];
    float psi = g_S[(size_t)a * (KK * KK) + e] * C;

    #pragma unroll
    for (int off = 16; off; off >>= 1)
        psi += __shfl_xor_sync(0xffffffffu, psi, off);
    if ((t & 31) == 0) red[t >> 5] = psi;
    __syncthreads();
    if (t == 0) {
        float tot = 0.f;
        #pragma unroll
        for (int ww = 0; ww < 8; ww++) tot += red[ww];
        g_psiPart[a * 4 + y] = tot;
    }
}

// ---------------------------------------------------------------------------
// Kernel 3b: combine. One block of 128 threads; thread a -> out[a].
// ---------------------------------------------------------------------------
__global__ void finalize_combine_kernel(float* __restrict__ out)
{
    const int a = threadIdx.x;
    float cnt = 0.f;
    #pragma unroll
    for (int ss = 0; ss < NS; ss++) cnt += g_partCnt[a * NS + ss];
    const float p = g_psiPart[a * 4 + 0] + g_psiPart[a * 4 + 1]
                  + g_psiPart[a * 4 + 2] + g_psiPart[a * 4 + 3];
    out[a] = (cnt >= 2.0f) ? p : 0.0f;
}

// ---------------------------------------------------------------------------
// R13 schedule + S hoist: side stream runs wreduce, reduce_op, computeS
// (all hidden under solve, ~22us of side work < 73us). Join before accum.
// solve is the 4th launch -> ncu target.
// ---------------------------------------------------------------------------
extern "C" void kernel_launch(void* const* d_in, const int* in_sizes, int n_in,
                              void* d_out, int out_size)
{
    const float* W  = (const float*)d_in[0];   // (N, M, G)
    const float* mu = (const float*)d_in[1];   // (N, G, K)
    const float* oc = (const float*)d_in[2];   // (N, G, K, K)
    const float* op = (const float*)d_in[3];   // (M, G, K, K)
    float* out = (float*)d_out;                // (M,)

    // fork
    cudaEventRecord(g_hx.evRoot, 0);
    cudaStreamWaitEvent(g_hx.side, g_hx.evRoot, 0);

    // side stream: W reduce + omega_parent reduce + S precompute
    wreduce_kernel<<<NN / 32, 256, 0, g_hx.side>>>(W);
    reduce_op_kernel<<<MM, 256, 0, g_hx.side>>>((const float4*)op);
    computeS_kernel<<<MM, 256, 0, g_hx.side>>>();

    // main stream: the big solve (4th launch -> ncu)
    solve_kernel<<<NN, 128>>>(oc, mu);

    // join
    cudaEventRecord(g_hx.evSide, g_hx.side);
    cudaStreamWaitEvent(0, g_hx.evSide, 0);

    accum_kernel<<<dim3(MM, NS), 128>>>();
    finalize_part_kernel<<<dim3(MM, 4), 256>>>();
    finalize_combine_kernel<<<1, MM>>>(out);
}